// round 11
// baseline (speedup 1.0000x reference)
#include <cuda_runtime.h>
#include <cuda_bf16.h>
#include <math.h>
#include <stdint.h>

// Problem constants (fixed by setup_inputs)
#define N_ROWS 8192
#define M_ROWS 8192
#define D_DIM  256
#define TOPK   32
#define RANK_TARGET 64          // candidate depth (safety margin over 32)
#define MAXCAND 256

// ---------------- static device scratch (allocation-guard legal) -----------
__device__ __align__(256) float          g_Z  [(size_t)N_ROWS * D_DIM];
__device__ __align__(256) __nv_bfloat16  g_Zb [(size_t)N_ROWS * D_DIM];
__device__ __align__(256) __nv_bfloat16  g_Yb [(size_t)M_ROWS * D_DIM];
__device__ __align__(256) __nv_bfloat16  g_Eb [(size_t)N_ROWS * M_ROWS];
__device__ __align__(256) float          g_rnx[N_ROWS];
__device__ __align__(256) float          g_rny[M_ROWS];

// ---------------- PTX helpers (arch-neutral: sm_80+ features only) ---------
__device__ __forceinline__ uint32_t smem_u32(const void* p) {
    uint32_t a;
    asm("{ .reg .u64 t; cvta.to.shared.u64 t, %1; cvt.u32.u64 %0, t; }"
        : "=r"(a) : "l"(p));
    return a;
}
#define CP_ASYNC16(dst, src) \
    asm volatile("cp.async.ca.shared.global [%0], [%1], 16;" :: "r"(dst), "l"(src))
#define CP_COMMIT() asm volatile("cp.async.commit_group;" ::: "memory")
#define CP_WAIT_ALL() asm volatile("cp.async.wait_group 0;" ::: "memory")

#define LDMATRIX_X4(r0, r1, r2, r3, addr) \
    asm volatile("ldmatrix.sync.aligned.m8n8.x4.shared.b16 {%0,%1,%2,%3}, [%4];" \
                 : "=r"(r0), "=r"(r1), "=r"(r2), "=r"(r3) : "r"(addr))

#define MMA_16816(c, a0, a1, a2, a3, b0, b1) \
    asm volatile("mma.sync.aligned.m16n8k16.row.col.f32.bf16.bf16.f32 " \
                 "{%0,%1,%2,%3}, {%4,%5,%6,%7}, {%8,%9}, {%0,%1,%2,%3};" \
                 : "+f"((c)[0]), "+f"((c)[1]), "+f"((c)[2]), "+f"((c)[3]) \
                 : "r"(a0), "r"(a1), "r"(a2), "r"(a3), "r"(b0), "r"(b1))

// ---------------- Kernel 1: Z = X @ W1 (fp32, exact path) -------------------
__global__ void z_gemm_kernel(const float* __restrict__ X,
                              const float* __restrict__ W) {
    __shared__ float As[16][68];
    __shared__ float Bs[16][68];
    const int m0 = blockIdx.x * 64;
    const int n0 = blockIdx.y * 64;
    const int tid = threadIdx.x;
    const int arow = tid >> 2, ak = (tid & 3) << 2;
    const int bk = tid >> 4,  bn = (tid & 15) << 2;
    const int tm = (tid >> 4) << 2, tn = (tid & 15) << 2;

    float acc[4][4] = {};
    for (int k0 = 0; k0 < D_DIM; k0 += 16) {
        float4 av = *(const float4*)(X + (size_t)(m0 + arow) * D_DIM + k0 + ak);
        float4 bv = *(const float4*)(W + (size_t)(k0 + bk) * D_DIM + n0 + bn);
        As[ak + 0][arow] = av.x; As[ak + 1][arow] = av.y;
        As[ak + 2][arow] = av.z; As[ak + 3][arow] = av.w;
        *(float4*)&Bs[bk][bn] = bv;
        __syncthreads();
#pragma unroll
        for (int k = 0; k < 16; k++) {
            float4 a4 = *(const float4*)&As[k][tm];
            float4 b4 = *(const float4*)&Bs[k][tn];
            float a[4] = {a4.x, a4.y, a4.z, a4.w};
            float b[4] = {b4.x, b4.y, b4.z, b4.w};
#pragma unroll
            for (int i = 0; i < 4; i++)
#pragma unroll
                for (int j = 0; j < 4; j++) acc[i][j] += a[i] * b[j];
        }
        __syncthreads();
    }
#pragma unroll
    for (int i = 0; i < 4; i++) {
        float4 v = {acc[i][0], acc[i][1], acc[i][2], acc[i][3]};
        *(float4*)(g_Z + (size_t)(m0 + tm + i) * D_DIM + n0 + tn) = v;
    }
}

// ---------------- Kernel 2: prep bf16 operands + inline norms ---------------
__global__ void __launch_bounds__(128) prep_kernel(const float* __restrict__ fx,
                                                   const float* __restrict__ fy) {
    __shared__ float s_w[4];
    __shared__ float s_rn;
    const int row = blockIdx.x;
    const int t = threadIdx.x;            // 128 threads, 2 floats each
    const int lane = t & 31, wrp = t >> 5;

    const float* normsrc;
    const float* valsrc;
    float* rnout;
    __nv_bfloat16* dst;
    if (blockIdx.y == 0) {
        normsrc = fx + (size_t)row * D_DIM;
        valsrc  = g_Z + (size_t)row * D_DIM;
        rnout = g_rnx; dst = g_Zb + (size_t)row * D_DIM;
    } else {
        normsrc = fy + (size_t)row * D_DIM;
        valsrc  = fy + (size_t)row * D_DIM;
        rnout = g_rny; dst = g_Yb + (size_t)row * D_DIM;
    }

    float2 nv = ((const float2*)normsrc)[t];
    float ss = nv.x * nv.x + nv.y * nv.y;
#pragma unroll
    for (int o = 16; o; o >>= 1) ss += __shfl_xor_sync(0xffffffffu, ss, o);
    if (lane == 0) s_w[wrp] = ss;
    __syncthreads();
    if (t == 0) s_rn = 1.0f / sqrtf(s_w[0] + s_w[1] + s_w[2] + s_w[3]);
    __syncthreads();
    const float rn = s_rn;

    float2 v = ((const float2*)valsrc)[t];
    v.x *= rn; v.y *= rn;
    ((__nv_bfloat162*)dst)[t] = __float22bfloat162_rn(v);
    if (t == 0) rnout[row] = rn;
}

// ---------------- Kernel 3: HMMA bf16 GEMM + zero out-tile ------------------
// CTA tile 128x128, 8 warps, warp tile 64x32 (R6 config, measured 159us).
// K=256 in 4 chunks of BK=64, cp.async 2-stage pipeline. 144B smem row stride.
// NEW: CTA streaming-zeroes its 128x128 tile of `out` in the prologue —
// hidden under the latency-bound mainloop (mma DRAM was 6.9%).
#define MMA_ROWELEMS  72
#define MMA_OPBYTES   (128 * MMA_ROWELEMS * 2)   // 18432
#define MMA_STAGE     (2 * MMA_OPBYTES)          // 36864
#define MMA_SMEM      (2 * MMA_STAGE)            // 73728

__global__ void __launch_bounds__(256) mma_kernel(float* __restrict__ out) {
    extern __shared__ char smem[];
    const int tid  = threadIdx.x;
    const int lane = tid & 31;
    const int warp = tid >> 5;
    const int wm   = warp >> 2;     // 0..1  (64-row slab)
    const int wn   = warp & 3;      // 0..3  (32-col slab)
    const int m0   = blockIdx.y * 128;
    const int n0   = blockIdx.x * 128;

    // zero this CTA's out tile (streaming stores; drain under mainloop)
    {
        const int zr = tid >> 1;              // 0..127
        const int zc = (tid & 1) << 4;        // float4 idx 0 or 16
        float4* zdst = (float4*)(out + (size_t)(m0 + zr) * M_ROWS + n0) + zc;
        const float4 z4 = {0.f, 0.f, 0.f, 0.f};
#pragma unroll
        for (int i = 0; i < 16; i++) __stcs(&zdst[i], z4);
    }

    const uint32_t sbase = smem_u32(smem);

    const int lr = tid >> 1;                 // 0..127 (one row per 2 threads)
    const int lc = (tid & 1) << 2;           // chunk base 0 or 4
    const uint32_t so = (uint32_t)(lr * 144 + lc * 16);
    const uint4* gA = (const uint4*)g_Zb;    // 32 uint4 per 256-elem row
    const uint4* gB = (const uint4*)g_Yb;
    const size_t gaRow = (size_t)(m0 + lr) * 32 + lc;
    const size_t gbRow = (size_t)(n0 + lr) * 32 + lc;

    float acc[4][4][4] = {};

    const uint32_t aLmBase = (uint32_t)((wm * 64 + (lane & 15)) * 144 + ((lane >> 4) << 4));
    const uint32_t bLmBase = (uint32_t)((wn * 32 + (lane & 15)) * 144 + ((lane >> 4) << 4));

    {   // prologue: stage 0, k-chunk 0
        uint32_t aDst = sbase;
        uint32_t bDst = aDst + MMA_OPBYTES;
#pragma unroll
        for (int c = 0; c < 4; c++) {
            CP_ASYNC16(aDst + so + c * 16, (const void*)(gA + gaRow + c));
            CP_ASYNC16(bDst + so + c * 16, (const void*)(gB + gbRow + c));
        }
        CP_COMMIT();
    }

    for (int kc = 0; kc < 4; kc++) {
        const int cur = kc & 1;
        CP_WAIT_ALL();
        __syncthreads();

        if (kc < 3) {                        // prefetch next k-chunk, other stage
            uint32_t aDst = sbase + (1 - cur) * MMA_STAGE;
            uint32_t bDst = aDst + MMA_OPBYTES;
            int kh = (kc + 1) * 8;
#pragma unroll
            for (int c = 0; c < 4; c++) {
                CP_ASYNC16(aDst + so + c * 16, (const void*)(gA + gaRow + kh + c));
                CP_ASYNC16(bDst + so + c * 16, (const void*)(gB + gbRow + kh + c));
            }
            CP_COMMIT();
        }

        const uint32_t aS = sbase + cur * MMA_STAGE + aLmBase;
        const uint32_t bS = sbase + cur * MMA_STAGE + MMA_OPBYTES + bLmBase;
#pragma unroll
        for (int kk = 0; kk < 4; kk++) {
            uint32_t bf[2][4];
#pragma unroll
            for (int nb = 0; nb < 2; nb++)
                LDMATRIX_X4(bf[nb][0], bf[nb][1], bf[nb][2], bf[nb][3],
                            bS + nb * (16 * 144) + kk * 32);
#pragma unroll
            for (int mi = 0; mi < 4; mi++) {
                uint32_t a0, a1, a2, a3;
                LDMATRIX_X4(a0, a1, a2, a3, aS + mi * (16 * 144) + kk * 32);
#pragma unroll
                for (int ni = 0; ni < 4; ni++)
                    MMA_16816(acc[mi][ni], a0, a1, a2, a3,
                              bf[ni >> 1][ni & 1], bf[ni >> 1][(ni & 1) + 2]);
            }
        }
        __syncthreads();
    }

    const int rBase = m0 + wm * 64 + (lane >> 2);
    const int cBase = n0 + wn * 32 + ((lane & 3) << 1);
#pragma unroll
    for (int mi = 0; mi < 4; mi++) {
#pragma unroll
        for (int ni = 0; ni < 4; ni++) {
            float* c = acc[mi][ni];
            int r = rBase + mi * 16;
            int col = cBase + ni * 8;
            float2 f0 = {c[0], c[1]};
            float2 f1 = {c[2], c[3]};
            __nv_bfloat162 h0 = __float22bfloat162_rn(f0);
            __nv_bfloat162 h1 = __float22bfloat162_rn(f1);
            *(uint32_t*)(g_Eb + (size_t)r * M_ROWS + col)       = *(uint32_t*)&h0;
            *(uint32_t*)(g_Eb + (size_t)(r + 8) * M_ROWS + col) = *(uint32_t*)&h1;
        }
    }
}

// ---------------- Kernel 4: select: int-bisect -> exact recompute -> rank ---
__global__ void __launch_bounds__(256) select_kernel(const float* __restrict__ fy,
                                                     float* __restrict__ out) {
    __shared__ float s_z[D_DIM];
    __shared__ int   s_wcnt[16][8];        // per-iteration bisect counts
    __shared__ int   s_cnt;
    __shared__ int   s_ccol[MAXCAND];
    __shared__ float s_cval[MAXCAND];
    __shared__ float s_max;
    __shared__ float s_exp[TOPK];
    __shared__ int   s_colsel[TOPK];

    const int row  = blockIdx.x;
    const int tid  = threadIdx.x;
    const int lane = tid & 31, wid = tid >> 5;

    // load approx row as monotonic 16-bit integer keys (32 per thread)
    int key[32];
    const uint4* erow = (const uint4*)(g_Eb + (size_t)row * M_ROWS);
#pragma unroll
    for (int li = 0; li < 4; li++) {
        uint4 u = erow[tid + (li << 8)];
        uint32_t w4[4] = {u.x, u.y, u.z, u.w};
#pragma unroll
        for (int j = 0; j < 4; j++) {
            uint32_t blo = w4[j] & 0xFFFFu;
            uint32_t bhi = w4[j] >> 16;
            key[li * 8 + 2 * j]     = (int)(blo ^ ((blo & 0x8000u) ? 0xFFFFu : 0x8000u));
            key[li * 8 + 2 * j + 1] = (int)(bhi ^ ((bhi & 0x8000u) ? 0xFFFFu : 0x8000u));
        }
    }
    s_z[tid] = g_Z[(size_t)row * D_DIM + tid];
    const float rnx = g_rnx[row];

    // integer bisection: largest T with count(key >= T) >= RANK_TARGET.
    // One barrier per iteration: counts go to per-iteration slots (no reset).
    int lo = 0, hi = 65536;
    int ncand = M_ROWS;
    for (int it = 0; it < 16; it++) {
        int mid = (lo + hi) >> 1;
        int c = 0;
#pragma unroll
        for (int i = 0; i < 32; i++) c += (key[i] >= mid);
#pragma unroll
        for (int o = 16; o; o >>= 1) c += __shfl_xor_sync(0xffffffffu, c, o);
        if (lane == 0) s_wcnt[it][wid] = c;
        __syncthreads();
        int cnt = 0;
#pragma unroll
        for (int w = 0; w < 8; w++) cnt += s_wcnt[it][w];
        if (cnt >= RANK_TARGET) { lo = mid; ncand = cnt; }
        else                    { hi = mid; }
    }
    const int T = lo;
    if (ncand > MAXCAND) ncand = MAXCAND;

    // gather candidate columns (cap MAXCAND)
    if (tid == 0) s_cnt = 0;
    __syncthreads();
#pragma unroll
    for (int li = 0; li < 4; li++)
#pragma unroll
        for (int e = 0; e < 8; e++) {
            if (key[li * 8 + e] >= T) {
                int p = atomicAdd(&s_cnt, 1);
                if (p < MAXCAND) s_ccol[p] = (tid + (li << 8)) * 8 + e;
            }
        }
    __syncthreads();

    // exact fp32 recompute: one WARP per candidate (lane-coalesced loads)
    for (int c = wid; c < ncand; c += 8) {
        int col = s_ccol[c];
        const float4* y4 = (const float4*)(fy + (size_t)col * D_DIM);
        const float4* z4 = (const float4*)s_z;
        float s = 0.f;
#pragma unroll
        for (int t = 0; t < 2; t++) {
            float4 a = z4[lane + 32 * t];
            float4 b = y4[lane + 32 * t];
            s += a.x * b.x + a.y * b.y + a.z * b.z + a.w * b.w;
        }
#pragma unroll
        for (int o = 16; o; o >>= 1) s += __shfl_xor_sync(0xffffffffu, s, o);
        if (lane == 0) s_cval[c] = s * rnx * g_rny[col];
    }
    __syncthreads();

    // exact rank scan (no barriers): rank by (value desc, col asc)
    int myrank = MAXCAND;
    float myv = 0.f; int myc = 0;
    if (tid < ncand) {
        myv = s_cval[tid]; myc = s_ccol[tid];
        int r = 0;
        for (int j = 0; j < ncand; j++) {
            float vj = s_cval[j]; int cj = s_ccol[j];
            r += (vj > myv) || (vj == myv && cj < myc);
        }
        myrank = r;
        if (r == 0) s_max = myv;
        if (r < TOPK) s_colsel[r] = myc;   // ranks unique -> no race
    }
    __syncthreads();

    // deterministic softmax over ranks 0..31
    if (myrank < TOPK) s_exp[myrank] = expf(myv - s_max);
    __syncthreads();
    if (tid < TOPK) {
        float e = s_exp[tid];
        float sum = e;
#pragma unroll
        for (int o = 16; o; o >>= 1) sum += __shfl_xor_sync(0xffffffffu, sum, o);
        int col = s_colsel[tid];
        if (col >= 0 && col < M_ROWS)
            out[(size_t)row * M_ROWS + col] = e / sum;
    }
}

// ---------------- launch ----------------------------------------------------
extern "C" void kernel_launch(void* const* d_in, const int* in_sizes, int n_in,
                              void* d_out, int out_size) {
    const float* feat_x = (const float*)d_in[0];
    const float* feat_y = (const float*)d_in[1];
    const float* W1     = (const float*)d_in[2];
    float* out = (float*)d_out;

    cudaFuncSetAttribute(mma_kernel,
                         cudaFuncAttributeMaxDynamicSharedMemorySize, MMA_SMEM);

    z_gemm_kernel<<<dim3(N_ROWS / 64, D_DIM / 64), 256>>>(feat_x, W1);
    prep_kernel<<<dim3(N_ROWS, 2), 128>>>(feat_x, feat_y);
    mma_kernel<<<dim3(M_ROWS / 128, N_ROWS / 128), 256, MMA_SMEM>>>(out);
    select_kernel<<<N_ROWS, 256>>>(feat_y, out);
}

// round 12
// speedup vs baseline: 1.3725x; 1.3725x over previous
#include <cuda_runtime.h>
#include <cuda_bf16.h>
#include <math.h>
#include <stdint.h>

// Problem constants (fixed by setup_inputs)
#define N_ROWS 8192
#define M_ROWS 8192
#define D_DIM  256
#define TOPK   32
#define RANK_TARGET 64          // candidate depth (safety margin over 32)
#define MAXCAND 256

// ---------------- static device scratch (allocation-guard legal) -----------
__device__ __align__(256) float          g_Z  [(size_t)N_ROWS * D_DIM];
__device__ __align__(256) __nv_bfloat16  g_Zb [(size_t)N_ROWS * D_DIM];
__device__ __align__(256) __nv_bfloat16  g_Yb [(size_t)M_ROWS * D_DIM];
__device__ __align__(256) __nv_bfloat16  g_Eb [(size_t)N_ROWS * M_ROWS];
__device__ __align__(256) float          g_rnx[N_ROWS];
__device__ __align__(256) float          g_rny[M_ROWS];

// ---------------- PTX helpers (arch-neutral: sm_80+ features only) ---------
__device__ __forceinline__ uint32_t smem_u32(const void* p) {
    uint32_t a;
    asm("{ .reg .u64 t; cvta.to.shared.u64 t, %1; cvt.u32.u64 %0, t; }"
        : "=r"(a) : "l"(p));
    return a;
}
#define CP_ASYNC16(dst, src) \
    asm volatile("cp.async.ca.shared.global [%0], [%1], 16;" :: "r"(dst), "l"(src))
#define CP_COMMIT() asm volatile("cp.async.commit_group;" ::: "memory")
#define CP_WAIT_ALL() asm volatile("cp.async.wait_group 0;" ::: "memory")

#define LDMATRIX_X4(r0, r1, r2, r3, addr) \
    asm volatile("ldmatrix.sync.aligned.m8n8.x4.shared.b16 {%0,%1,%2,%3}, [%4];" \
                 : "=r"(r0), "=r"(r1), "=r"(r2), "=r"(r3) : "r"(addr))

#define MMA_16816(c, a0, a1, a2, a3, b0, b1) \
    asm volatile("mma.sync.aligned.m16n8k16.row.col.f32.bf16.bf16.f32 " \
                 "{%0,%1,%2,%3}, {%4,%5,%6,%7}, {%8,%9}, {%0,%1,%2,%3};" \
                 : "+f"((c)[0]), "+f"((c)[1]), "+f"((c)[2]), "+f"((c)[3]) \
                 : "r"(a0), "r"(a1), "r"(a2), "r"(a3), "r"(b0), "r"(b1))

// ---------------- Kernel 1: Z = X @ W1 (fp32, exact path) -------------------
__global__ void z_gemm_kernel(const float* __restrict__ X,
                              const float* __restrict__ W) {
    __shared__ float As[16][68];
    __shared__ float Bs[16][68];
    const int m0 = blockIdx.x * 64;
    const int n0 = blockIdx.y * 64;
    const int tid = threadIdx.x;
    const int arow = tid >> 2, ak = (tid & 3) << 2;
    const int bk = tid >> 4,  bn = (tid & 15) << 2;
    const int tm = (tid >> 4) << 2, tn = (tid & 15) << 2;

    float acc[4][4] = {};
    for (int k0 = 0; k0 < D_DIM; k0 += 16) {
        float4 av = *(const float4*)(X + (size_t)(m0 + arow) * D_DIM + k0 + ak);
        float4 bv = *(const float4*)(W + (size_t)(k0 + bk) * D_DIM + n0 + bn);
        As[ak + 0][arow] = av.x; As[ak + 1][arow] = av.y;
        As[ak + 2][arow] = av.z; As[ak + 3][arow] = av.w;
        *(float4*)&Bs[bk][bn] = bv;
        __syncthreads();
#pragma unroll
        for (int k = 0; k < 16; k++) {
            float4 a4 = *(const float4*)&As[k][tm];
            float4 b4 = *(const float4*)&Bs[k][tn];
            float a[4] = {a4.x, a4.y, a4.z, a4.w};
            float b[4] = {b4.x, b4.y, b4.z, b4.w};
#pragma unroll
            for (int i = 0; i < 4; i++)
#pragma unroll
                for (int j = 0; j < 4; j++) acc[i][j] += a[i] * b[j];
        }
        __syncthreads();
    }
#pragma unroll
    for (int i = 0; i < 4; i++) {
        float4 v = {acc[i][0], acc[i][1], acc[i][2], acc[i][3]};
        *(float4*)(g_Z + (size_t)(m0 + tm + i) * D_DIM + n0 + tn) = v;
    }
}

// ---------------- Kernel 2: prep bf16 operands + inline norms ---------------
__global__ void __launch_bounds__(128) prep_kernel(const float* __restrict__ fx,
                                                   const float* __restrict__ fy) {
    __shared__ float s_w[4];
    __shared__ float s_rn;
    const int row = blockIdx.x;
    const int t = threadIdx.x;            // 128 threads, 2 floats each
    const int lane = t & 31, wrp = t >> 5;

    const float* normsrc;
    const float* valsrc;
    float* rnout;
    __nv_bfloat16* dst;
    if (blockIdx.y == 0) {
        normsrc = fx + (size_t)row * D_DIM;
        valsrc  = g_Z + (size_t)row * D_DIM;
        rnout = g_rnx; dst = g_Zb + (size_t)row * D_DIM;
    } else {
        normsrc = fy + (size_t)row * D_DIM;
        valsrc  = fy + (size_t)row * D_DIM;
        rnout = g_rny; dst = g_Yb + (size_t)row * D_DIM;
    }

    float2 nv = ((const float2*)normsrc)[t];
    float ss = nv.x * nv.x + nv.y * nv.y;
#pragma unroll
    for (int o = 16; o; o >>= 1) ss += __shfl_xor_sync(0xffffffffu, ss, o);
    if (lane == 0) s_w[wrp] = ss;
    __syncthreads();
    if (t == 0) s_rn = 1.0f / sqrtf(s_w[0] + s_w[1] + s_w[2] + s_w[3]);
    __syncthreads();
    const float rn = s_rn;

    float2 v = ((const float2*)valsrc)[t];
    v.x *= rn; v.y *= rn;
    ((__nv_bfloat162*)dst)[t] = __float22bfloat162_rn(v);
    if (t == 0) rnout[row] = rn;
}

// ---------------- Kernel 3: HMMA bf16 GEMM (exact R6 config, 159us) ---------
#define MMA_ROWELEMS  72
#define MMA_OPBYTES   (128 * MMA_ROWELEMS * 2)   // 18432
#define MMA_STAGE     (2 * MMA_OPBYTES)          // 36864
#define MMA_SMEM      (2 * MMA_STAGE)            // 73728

__global__ void __launch_bounds__(256) mma_kernel() {
    extern __shared__ char smem[];
    const int tid  = threadIdx.x;
    const int lane = tid & 31;
    const int warp = tid >> 5;
    const int wm   = warp >> 2;     // 0..1  (64-row slab)
    const int wn   = warp & 3;      // 0..3  (32-col slab)
    const int m0   = blockIdx.y * 128;
    const int n0   = blockIdx.x * 128;

    const uint32_t sbase = smem_u32(smem);

    const int lr = tid >> 1;                 // 0..127 (one row per 2 threads)
    const int lc = (tid & 1) << 2;           // chunk base 0 or 4
    const uint32_t so = (uint32_t)(lr * 144 + lc * 16);
    const uint4* gA = (const uint4*)g_Zb;    // 32 uint4 per 256-elem row
    const uint4* gB = (const uint4*)g_Yb;
    const size_t gaRow = (size_t)(m0 + lr) * 32 + lc;
    const size_t gbRow = (size_t)(n0 + lr) * 32 + lc;

    float acc[4][4][4] = {};

    const uint32_t aLmBase = (uint32_t)((wm * 64 + (lane & 15)) * 144 + ((lane >> 4) << 4));
    const uint32_t bLmBase = (uint32_t)((wn * 32 + (lane & 15)) * 144 + ((lane >> 4) << 4));

    {   // prologue: stage 0, k-chunk 0
        uint32_t aDst = sbase;
        uint32_t bDst = aDst + MMA_OPBYTES;
#pragma unroll
        for (int c = 0; c < 4; c++) {
            CP_ASYNC16(aDst + so + c * 16, (const void*)(gA + gaRow + c));
            CP_ASYNC16(bDst + so + c * 16, (const void*)(gB + gbRow + c));
        }
        CP_COMMIT();
    }

    for (int kc = 0; kc < 4; kc++) {
        const int cur = kc & 1;
        CP_WAIT_ALL();
        __syncthreads();

        if (kc < 3) {                        // prefetch next k-chunk, other stage
            uint32_t aDst = sbase + (1 - cur) * MMA_STAGE;
            uint32_t bDst = aDst + MMA_OPBYTES;
            int kh = (kc + 1) * 8;
#pragma unroll
            for (int c = 0; c < 4; c++) {
                CP_ASYNC16(aDst + so + c * 16, (const void*)(gA + gaRow + kh + c));
                CP_ASYNC16(bDst + so + c * 16, (const void*)(gB + gbRow + kh + c));
            }
            CP_COMMIT();
        }

        const uint32_t aS = sbase + cur * MMA_STAGE + aLmBase;
        const uint32_t bS = sbase + cur * MMA_STAGE + MMA_OPBYTES + bLmBase;
#pragma unroll
        for (int kk = 0; kk < 4; kk++) {
            uint32_t bf[2][4];
#pragma unroll
            for (int nb = 0; nb < 2; nb++)
                LDMATRIX_X4(bf[nb][0], bf[nb][1], bf[nb][2], bf[nb][3],
                            bS + nb * (16 * 144) + kk * 32);
#pragma unroll
            for (int mi = 0; mi < 4; mi++) {
                uint32_t a0, a1, a2, a3;
                LDMATRIX_X4(a0, a1, a2, a3, aS + mi * (16 * 144) + kk * 32);
#pragma unroll
                for (int ni = 0; ni < 4; ni++)
                    MMA_16816(acc[mi][ni], a0, a1, a2, a3,
                              bf[ni >> 1][ni & 1], bf[ni >> 1][(ni & 1) + 2]);
            }
        }
        __syncthreads();
    }

    const int rBase = m0 + wm * 64 + (lane >> 2);
    const int cBase = n0 + wn * 32 + ((lane & 3) << 1);
#pragma unroll
    for (int mi = 0; mi < 4; mi++) {
#pragma unroll
        for (int ni = 0; ni < 4; ni++) {
            float* c = acc[mi][ni];
            int r = rBase + mi * 16;
            int col = cBase + ni * 8;
            float2 f0 = {c[0], c[1]};
            float2 f1 = {c[2], c[3]};
            __nv_bfloat162 h0 = __float22bfloat162_rn(f0);
            __nv_bfloat162 h1 = __float22bfloat162_rn(f1);
            *(uint32_t*)(g_Eb + (size_t)r * M_ROWS + col)       = *(uint32_t*)&h0;
            *(uint32_t*)(g_Eb + (size_t)(r + 8) * M_ROWS + col) = *(uint32_t*)&h1;
        }
    }
}

// ---------------- Kernel 4: select: radix-hist -> exact recompute -> scatter
// Keys: bf16 -> monotone u16 via packed branchless transform.
// Threshold T = largest value with count(key >= T) >= RANK_TARGET, found by
// 2-pass byte histogram (identical result to bisection).
__global__ void __launch_bounds__(256) select_kernel(const float* __restrict__ fy,
                                                     float* __restrict__ out) {
    __shared__ float s_z[D_DIM];
    __shared__ int   s_hist1[256];
    __shared__ int   s_hist2[256];
    __shared__ int   s_b0, s_base1, s_T, s_ncand;
    __shared__ int   s_cnt;
    __shared__ int   s_ccol[MAXCAND];
    __shared__ float s_cval[MAXCAND];
    __shared__ float s_max;
    __shared__ float s_exp[TOPK];
    __shared__ int   s_colsel[TOPK];

    const int row  = blockIdx.x;
    const int tid  = threadIdx.x;
    const int lane = tid & 31, wid = tid >> 5;
    const unsigned FULL = 0xffffffffu;

    // zero hists + init
    s_hist1[tid] = 0;
    if (tid < 256) s_hist2[tid] = 0;
    if (tid == 0) s_cnt = 0;

    // load row as packed monotone u16 keys: per half, sign? ~x : x|0x8000
    uint32_t kp[16];
    const uint4* erow = (const uint4*)(g_Eb + (size_t)row * M_ROWS);
#pragma unroll
    for (int li = 0; li < 4; li++) {
        uint4 u = erow[tid + (li << 8)];
        uint32_t w4[4] = {u.x, u.y, u.z, u.w};
#pragma unroll
        for (int j = 0; j < 4; j++) {
            uint32_t w = w4[j];
            uint32_t sgn = w & 0x80008000u;
            kp[li * 4 + j] = w ^ ((sgn - (sgn >> 15)) | 0x80008000u);
        }
    }
    s_z[tid] = g_Z[(size_t)row * D_DIM + tid];
    const float rnx = g_rnx[row];
    __syncthreads();

    // ---- pass 1: histogram high bytes --------------------------------------
#pragma unroll
    for (int i = 0; i < 16; i++) {
        uint32_t w = kp[i];
        atomicAdd(&s_hist1[(w >> 8) & 0xFFu], 1);
        atomicAdd(&s_hist1[w >> 24], 1);
    }
    __syncthreads();

    if (wid == 0) {          // warp-0 suffix scan over 256 bins
        int b8[8], part = 0;
#pragma unroll
        for (int j = 0; j < 8; j++) { b8[j] = s_hist1[lane * 8 + j]; part += b8[j]; }
        int s = part;
#pragma unroll
        for (int o = 1; o < 32; o <<= 1) {
            int t = __shfl_down_sync(FULL, s, o);
            if (lane + o < 32) s += t;
        }
        int shigher = __shfl_down_sync(FULL, s, 1);
        if (lane == 31) shigher = 0;
        unsigned ball = __ballot_sync(FULL, s >= RANK_TARGET);
        int lsel = 31 - __clz(ball);           // exists: s(0)=8192 >= 64
        if (lane == lsel) {
            int cum = shigher;
            for (int j = 7; j >= 0; j--) {
                int c = cum + b8[j];
                if (c >= RANK_TARGET) { s_b0 = lane * 8 + j; s_base1 = cum; break; }
                cum = c;
            }
        }
    }
    __syncthreads();
    const int b0 = s_b0;
    const int base1 = s_base1;

    // ---- pass 2: histogram low bytes within bin b0 --------------------------
#pragma unroll
    for (int i = 0; i < 16; i++) {
        uint32_t w = kp[i];
        uint32_t lo = w & 0xFFFFu, hi = w >> 16;
        if ((int)(lo >> 8) == b0) atomicAdd(&s_hist2[lo & 0xFFu], 1);
        if ((int)(hi >> 8) == b0) atomicAdd(&s_hist2[hi & 0xFFu], 1);
    }
    __syncthreads();

    if (wid == 0) {
        int b8[8], part = 0;
#pragma unroll
        for (int j = 0; j < 8; j++) { b8[j] = s_hist2[lane * 8 + j]; part += b8[j]; }
        int s = part;
#pragma unroll
        for (int o = 1; o < 32; o <<= 1) {
            int t = __shfl_down_sync(FULL, s, o);
            if (lane + o < 32) s += t;
        }
        int shigher = __shfl_down_sync(FULL, s, 1);
        if (lane == 31) shigher = 0;
        unsigned ball = __ballot_sync(FULL, base1 + s >= RANK_TARGET);
        int lsel = 31 - __clz(ball);           // exists at L=0
        if (lane == lsel) {
            int cum = shigher;
            for (int j = 7; j >= 0; j--) {
                int c = cum + b8[j];
                if (base1 + c >= RANK_TARGET) {
                    s_T = (b0 << 8) | (lane * 8 + j);
                    s_ncand = base1 + c;
                    break;
                }
                cum = c;
            }
        }
    }
    __syncthreads();
    const uint32_t T = (uint32_t)s_T;
    int ncand = s_ncand;
    if (ncand > MAXCAND) ncand = MAXCAND;

    // ---- gather candidate columns -------------------------------------------
#pragma unroll
    for (int i = 0; i < 16; i++) {
        uint32_t w = kp[i];
        uint32_t lo = w & 0xFFFFu, hi = w >> 16;
        int li = i >> 2, j = i & 3;
        int colbase = (tid + (li << 8)) * 8 + 2 * j;
        if (lo >= T) {
            int p = atomicAdd(&s_cnt, 1);
            if (p < MAXCAND) s_ccol[p] = colbase;
        }
        if (hi >= T) {
            int p = atomicAdd(&s_cnt, 1);
            if (p < MAXCAND) s_ccol[p] = colbase + 1;
        }
    }
    __syncthreads();

    // ---- exact fp32 recompute: one WARP per candidate (coalesced) -----------
    for (int c = wid; c < ncand; c += 8) {
        int col = s_ccol[c];
        const float4* y4 = (const float4*)(fy + (size_t)col * D_DIM);
        const float4* z4 = (const float4*)s_z;
        float s = 0.f;
#pragma unroll
        for (int t = 0; t < 2; t++) {
            float4 a = z4[lane + 32 * t];
            float4 b = y4[lane + 32 * t];
            s += a.x * b.x + a.y * b.y + a.z * b.z + a.w * b.w;
        }
#pragma unroll
        for (int o = 16; o; o >>= 1) s += __shfl_xor_sync(FULL, s, o);
        if (lane == 0) s_cval[c] = s * rnx * g_rny[col];
    }
    __syncthreads();

    // ---- exact rank by (value desc, col asc); ranks unique -------------------
    int myrank = MAXCAND;
    float myv = 0.f; int myc = 0;
    if (tid < ncand) {
        myv = s_cval[tid]; myc = s_ccol[tid];
        int r = 0;
        for (int j = 0; j < ncand; j++) {
            float vj = s_cval[j]; int cj = s_ccol[j];
            r += (vj > myv) || (vj == myv && cj < myc);
        }
        myrank = r;
        if (r == 0) s_max = myv;
        if (r < TOPK) s_colsel[r] = myc;
    }
    __syncthreads();
    if (myrank < TOPK) s_exp[myrank] = expf(myv - s_max);

    // ---- zero output row (hidden under latency) + scatter --------------------
    float* orow = out + (size_t)row * M_ROWS;
    const float4 z4v = {0.f, 0.f, 0.f, 0.f};
#pragma unroll
    for (int t = 0; t < 8; t++)
        __stcs(&((float4*)orow)[tid + (t << 8)], z4v);
    __syncthreads();

    if (tid < TOPK) {
        float e = s_exp[tid];
        float sum = e;
#pragma unroll
        for (int o = 16; o; o >>= 1) sum += __shfl_xor_sync(FULL, sum, o);
        int col = s_colsel[tid];
        if (col >= 0 && col < M_ROWS)
            orow[col] = e / sum;
    }
}

// ---------------- launch ----------------------------------------------------
extern "C" void kernel_launch(void* const* d_in, const int* in_sizes, int n_in,
                              void* d_out, int out_size) {
    const float* feat_x = (const float*)d_in[0];
    const float* feat_y = (const float*)d_in[1];
    const float* W1     = (const float*)d_in[2];
    float* out = (float*)d_out;

    cudaFuncSetAttribute(mma_kernel,
                         cudaFuncAttributeMaxDynamicSharedMemorySize, MMA_SMEM);

    z_gemm_kernel<<<dim3(N_ROWS / 64, D_DIM / 64), 256>>>(feat_x, W1);
    prep_kernel<<<dim3(N_ROWS, 2), 128>>>(feat_x, feat_y);
    mma_kernel<<<dim3(M_ROWS / 128, N_ROWS / 128), 256, MMA_SMEM>>>();
    select_kernel<<<N_ROWS, 256>>>(feat_y, out);
}